// round 11
// baseline (speedup 1.0000x reference)
#include <cuda_runtime.h>
#include <cuda_fp16.h>
#include <mma.h>
#include <cstdint>
#include <cstddef>

using namespace nvcuda;
namespace wx = nvcuda::wmma;

#define NB 256
#define HD 1024
#define DD 256
#define TT 128

// ---- persistent step kernel geometry (8 warps, warp tile 32x32) ----
#define NTHR 256
#define KT2 64                    // k per chunk
#define NCH (HD / KT2)            // 16 chunks
#define LDA 72                    // A smem row stride (halves)
#define LDB 1032                  // B smem row stride (halves)
#define STGA (128 * LDA)          // halves per A stage (9216)
#define SMB_OFF (3 * STGA)
#define PERS_SMEM ((3 * STGA + 64 * LDB) * 2)   // 187392 B
#define LDG 68                    // gates smem row stride (floats); aliases A stages

// ---- fc kernel geometry ----
#define KT 32
#define NC (HD / KT)
#define LDTH 40
#define STG_A (128 * LDTH)
#define STG_B (64 * LDTH)
#define STG_H (STG_A + STG_B)
#define FC_SMEM (3 * STG_H * 2)

// ---------------- static device scratch ----------------
__device__ __half g_Wc[4096 * HD];              // gate-permuted (Wih+Whh)  8 MB
__device__ __half g_Wp[4096 * HD];              // gate-permuted Wih        8 MB
__device__ __half g_Wfc[DD * HD];
__device__ __half g_x0[NB * HD];
__device__ float  g_bp[4096];
__device__ __half g_h[(size_t)TT * NB * HD];    // hidden history fp16 (64 MB)
__device__ __align__(256) unsigned g_flags[128]; // [by*64 + bx]: steps completed

// fast pointwise via MUFU paths
__device__ __forceinline__ float sigm(float z) {
    return __fdividef(1.0f, 1.0f + __expf(-z));
}
__device__ __forceinline__ float ftanh(float z) {
    return __fdividef(2.0f, 1.0f + __expf(-2.0f * z)) - 1.0f;
}

#define CP16(saddr, gptr) \
    asm volatile("cp.async.cg.shared.global [%0], [%1], 16;" :: "r"(saddr), "l"(gptr) : "memory")
#define CP_COMMIT() asm volatile("cp.async.commit_group;" ::: "memory")

// ---------------- prep ----------------
__global__ void prep_kernel(const float* __restrict__ Wih, const float* __restrict__ Whh,
                            const float* __restrict__ bih, const float* __restrict__ bhh,
                            const float* __restrict__ Wfc, const float* __restrict__ hT) {
    size_t idx = (size_t)blockIdx.x * 256 + threadIdx.x;
    if (idx < (size_t)4096 * HD) {
        int k = (int)(idx & (HD - 1));
        int rowp = (int)(idx >> 10);            // permuted gate row: j*4 + G
        int j = rowp >> 2, G = rowp & 3;
        size_t src = (size_t)(G * HD + j) * HD + k;
        float a = Wih[src];
        g_Wp[idx] = __float2half_rn(a);
        g_Wc[idx] = __float2half_rn(a + Whh[src]);
    }
    if (idx < (size_t)DD * HD) g_Wfc[idx] = __float2half_rn(Wfc[idx]);
    if (idx < (size_t)NB * HD) g_x0[idx] = __float2half_rn(hT[idx]);
    if (idx < 4096) {
        int j = (int)(idx >> 2), G = (int)(idx & 3);
        g_bp[idx] = bih[G * HD + j] + bhh[G * HD + j];
    }
    if (idx < 128) g_flags[idx] = 0u;           // reset dataflow flags each launch
}

// ---------------- persistent LSTM ----------------
// grid (64, 2): n0 = bx*64 permuted gate cols (16 units), m0 = by*128 batch rows.
// 8 warps, warp tile 32x32; 3-stage cp.async pipeline (R9-proven mainloop).
// Sync: distributed flag barrier per batch half (release-store arrive, acquire-poll wait).
__global__ void __launch_bounds__(NTHR) lstm_persist() {
    extern __shared__ __half smh[];
    __half* smB = smh + SMB_OFF;
    float* gates = (float*)smh;                 // aliases A stages between steps

    const int tid = (int)threadIdx.x;
    const int w = tid >> 5;
    const int wm0 = (w & 3) * 32;
    const int wn0 = (w >> 2) * 32;
    const int bx = (int)blockIdx.x;
    const int by = (int)blockIdx.y;
    const size_t n0 = (size_t)bx * 64;
    const size_t m0 = (size_t)by * 128;

    const int ur = tid & 3;                     // unit quad
    const int rr = tid >> 2;                    // 0..63
    const int j0 = (int)(n0 >> 2);              // global hidden-unit base

    auto loadB = [&](const __half* __restrict__ Wsrc) {
        uint32_t sB = (uint32_t)__cvta_generic_to_shared(smB);
#pragma unroll
        for (int i = 0; i < 32; ++i) {
            int p = tid + i * NTHR;             // 0..8191
            int r = p >> 7;
            int sg = p & 127;
            CP16(sB + (uint32_t)(r * LDB + sg * 8) * 2u, Wsrc + (n0 + (size_t)r) * HD + sg * 8);
        }
        CP_COMMIT();
    };

    loadB(g_Wp);
    asm volatile("cp.async.wait_group 0;" ::: "memory");
    __syncthreads();

    float4 bq[4];
#pragma unroll
    for (int q = 0; q < 4; ++q)
        bq[q] = *(const float4*)(g_bp + n0 + (ur * 4 + q) * 4);

    float creg[8];
#pragma unroll
    for (int i = 0; i < 8; ++i) creg[i] = 0.0f;

    for (int t = 0; t < TT; ++t) {
        const __half* A = (t == 0) ? g_x0 : (g_h + (size_t)(t - 1) * NB * HD);

        // ---- wait: all 64 CTAs of this half finished step t-1 (one flag per lane) ----
        if (t > 0) {
            if (tid < 64) {
                const unsigned* f = g_flags + by * 64 + tid;
                unsigned v;
                int spins = 0;
                while (true) {
                    asm volatile("ld.acquire.gpu.global.u32 %0, [%1];" : "=r"(v) : "l"(f));
                    if (v >= (unsigned)t) break;
                    if (++spins > 8) __nanosleep(40);
                }
            }
            __syncthreads();
        }

        auto loadA = [&](int kc) {
            uint32_t sA = (uint32_t)__cvta_generic_to_shared(smh + (kc % 3) * STGA);
            const __half* gA = A + m0 * HD + (size_t)kc * KT2;
#pragma unroll
            for (int i = 0; i < 4; ++i) {
                int p = tid + i * NTHR;         // 0..1023
                int r = p >> 3;
                int sg = p & 7;
                CP16(sA + (uint32_t)(r * LDA + sg * 8) * 2u, gA + (size_t)r * HD + sg * 8);
            }
            CP_COMMIT();
        };

        wx::fragment<wx::accumulator, 16, 16, 16, float> cf[2][2];
#pragma unroll
        for (int i = 0; i < 2; ++i)
#pragma unroll
            for (int j = 0; j < 2; ++j) wx::fill_fragment(cf[i][j], 0.0f);

        loadA(0);
        loadA(1);

        for (int kc = 0; kc < NCH; ++kc) {
            if (kc < NCH - 1) asm volatile("cp.async.wait_group 1;" ::: "memory");
            else              asm volatile("cp.async.wait_group 0;" ::: "memory");
            __syncthreads();
            if (kc + 2 < NCH) loadA(kc + 2);

            const __half* smA = smh + (kc % 3) * STGA;
#pragma unroll
            for (int ks = 0; ks < 4; ++ks) {
                wx::fragment<wx::matrix_a, 16, 16, 16, __half, wx::row_major> af[2];
                wx::fragment<wx::matrix_b, 16, 16, 16, __half, wx::col_major> bf[2];
#pragma unroll
                for (int i = 0; i < 2; ++i)
                    wx::load_matrix_sync(af[i], smA + (wm0 + i * 16) * LDA + ks * 16, LDA);
#pragma unroll
                for (int j = 0; j < 2; ++j)
                    wx::load_matrix_sync(bf[j], smB + (wn0 + j * 16) * LDB + kc * KT2 + ks * 16, LDB);
#pragma unroll
                for (int i = 0; i < 2; ++i)
#pragma unroll
                    for (int j = 0; j < 2; ++j)
                        wx::mma_sync(cf[i][j], af[i], bf[j], cf[i][j]);
            }
        }

        __syncthreads();     // A stages free; alias as gates
#pragma unroll
        for (int i = 0; i < 2; ++i)
#pragma unroll
            for (int j = 0; j < 2; ++j)
                wx::store_matrix_sync(gates + (wm0 + i * 16) * LDG + wn0 + j * 16,
                                      cf[i][j], LDG, wx::mem_row_major);
        __syncthreads();

        // swap in combined weights after step 0 (overlaps epilogue)
        if (t == 0) loadB(g_Wc);

        // pointwise epilogue; c stays in registers
        __half* hbase = g_h + (size_t)t * NB * HD;
#pragma unroll
        for (int p = 0; p < 2; ++p) {
            int r = rr + p * 64;
            size_t m = m0 + r;
            __half hv[4];
#pragma unroll
            for (int q = 0; q < 4; ++q) {
                float4 gv = *(const float4*)(gates + r * LDG + (ur * 4 + q) * 4);
                const float* bb = &bq[q].x;
                float iv = sigm(gv.x + bb[0]);
                float fv = sigm(gv.y + bb[1]);
                float gg = ftanh(gv.z + bb[2]);
                float ov = sigm(gv.w + bb[3]);
                float c = fmaf(fv, creg[p * 4 + q], iv * gg);
                creg[p * 4 + q] = c;
                hv[q] = __float2half_rn(ov * ftanh(c));
            }
            *(uint2*)(hbase + m * HD + j0 + ur * 4) = *(uint2*)hv;
        }

        if (t == 0) asm volatile("cp.async.wait_group 0;" ::: "memory");  // retire B swap

        // ---- arrive: h[t] published. Distinct address per CTA; release is cumulative
        // over the happens-before established by the preceding __syncthreads. ----
        __syncthreads();
        if (tid == 0) {
            asm volatile("st.release.gpu.global.u32 [%0], %1;"
                         :: "l"(g_flags + by * 64 + bx), "r"((unsigned)(t + 1)) : "memory");
        }
    }
}

// ---------------- FC: out[32768,256] = h @ Wfc^T + b ----------------
__device__ __forceinline__ void gemm16_fc(const __half* __restrict__ A, size_t m0,
                                          const __half* __restrict__ B, size_t n0,
                                          __half* smh, float* gates) {
    const int tid = (int)threadIdx.x;
    const int w = tid >> 5;
    const int wm0 = (w & 3) * 32;
    const int wn0 = (w >> 2) * 32;

    wx::fragment<wx::accumulator, 16, 16, 16, float> cf[2][2];
#pragma unroll
    for (int i = 0; i < 2; ++i)
#pragma unroll
        for (int j = 0; j < 2; ++j) wx::fill_fragment(cf[i][j], 0.0f);

    auto load_chunk = [&](int kc) {
        __half* smA = smh + (kc % 3) * STG_H;
        __half* smB = smA + STG_A;
        uint32_t sA = (uint32_t)__cvta_generic_to_shared(smA);
        uint32_t sB = (uint32_t)__cvta_generic_to_shared(smB);
        const __half* gA = A + m0 * HD + (size_t)kc * KT;
        const __half* gB = B + n0 * HD + (size_t)kc * KT;
#pragma unroll
        for (int i = 0; i < 2; ++i) {
            int p = tid + i * 256;
            int r = p >> 2, seg = p & 3;
            CP16(sA + (uint32_t)(r * LDTH + seg * 8) * 2u, gA + (size_t)r * HD + seg * 8);
        }
        {
            int r = tid >> 2, seg = tid & 3;
            CP16(sB + (uint32_t)(r * LDTH + seg * 8) * 2u, gB + (size_t)r * HD + seg * 8);
        }
        CP_COMMIT();
    };

    load_chunk(0);
    load_chunk(1);

    for (int kc = 0; kc < NC; ++kc) {
        if (kc < NC - 1) asm volatile("cp.async.wait_group 1;" ::: "memory");
        else             asm volatile("cp.async.wait_group 0;" ::: "memory");
        __syncthreads();
        if (kc + 2 < NC) load_chunk(kc + 2);

        __half* smA = smh + (kc % 3) * STG_H;
        __half* smB = smA + STG_A;
#pragma unroll
        for (int ks = 0; ks < 2; ++ks) {
            wx::fragment<wx::matrix_a, 16, 16, 16, __half, wx::row_major> af[2];
            wx::fragment<wx::matrix_b, 16, 16, 16, __half, wx::col_major> bf[2];
#pragma unroll
            for (int i = 0; i < 2; ++i)
                wx::load_matrix_sync(af[i], smA + (wm0 + i * 16) * LDTH + ks * 16, LDTH);
#pragma unroll
            for (int j = 0; j < 2; ++j)
                wx::load_matrix_sync(bf[j], smB + (wn0 + j * 16) * LDTH + ks * 16, LDTH);
#pragma unroll
            for (int i = 0; i < 2; ++i)
#pragma unroll
                for (int j = 0; j < 2; ++j)
                    wx::mma_sync(cf[i][j], af[i], bf[j], cf[i][j]);
        }
    }

    __syncthreads();
#pragma unroll
    for (int i = 0; i < 2; ++i)
#pragma unroll
        for (int j = 0; j < 2; ++j)
            wx::store_matrix_sync(gates + (wm0 + i * 16) * LDG + wn0 + j * 16,
                                  cf[i][j], LDG, wx::mem_row_major);
    __syncthreads();
}

__global__ void __launch_bounds__(256) fc_kernel(const float* __restrict__ bfc,
                                                 float* __restrict__ out) {
    extern __shared__ __half smh[];
    float* gates = (float*)smh;
    size_t n0 = (size_t)blockIdx.x * 64;
    size_t m0 = (size_t)blockIdx.y * 128;

    gemm16_fc(g_h, m0, g_Wfc, n0, smh, gates);

    const int tid = (int)threadIdx.x;
    const int cg = tid & 3;
    const int rr = tid >> 2;
#pragma unroll
    for (int p = 0; p < 2; ++p) {
        int r = rr + p * 64;
        size_t m = m0 + r;
#pragma unroll
        for (int q = 0; q < 4; ++q) {
            int c = cg * 16 + q * 4;
            float4 gv = *(const float4*)(gates + r * LDG + c);
            float4 bv = *(const float4*)(bfc + n0 + c);
            gv.x += bv.x; gv.y += bv.y; gv.z += bv.z; gv.w += bv.w;
            *(float4*)(out + m * DD + n0 + c) = gv;
        }
    }
}

// ---------------- launch ----------------
extern "C" void kernel_launch(void* const* d_in, const int* in_sizes, int n_in,
                              void* d_out, int out_size) {
    const float* hT  = (const float*)d_in[0];
    // d_in[1] = t (int32) — fixed 128 for this problem
    const float* Wih = (const float*)d_in[2];
    const float* Whh = (const float*)d_in[3];
    const float* bih = (const float*)d_in[4];
    const float* bhh = (const float*)d_in[5];
    const float* Wfc = (const float*)d_in[6];
    const float* bfc = (const float*)d_in[7];
    float* out = (float*)d_out;

    cudaFuncSetAttribute(lstm_persist, cudaFuncAttributeMaxDynamicSharedMemorySize, PERS_SMEM);
    cudaFuncSetAttribute(fc_kernel, cudaFuncAttributeMaxDynamicSharedMemorySize, FC_SMEM);

    prep_kernel<<<(4096 * HD) / 256, 256>>>(Wih, Whh, bih, bhh, Wfc, hT);

    lstm_persist<<<dim3(64, 2), NTHR, PERS_SMEM>>>();

    fc_kernel<<<dim3(4, 256), 256, FC_SMEM>>>(bfc, out);
}

// round 12
// speedup vs baseline: 1.1770x; 1.1770x over previous
#include <cuda_runtime.h>
#include <cuda_fp16.h>
#include <mma.h>
#include <cstdint>
#include <cstddef>

using namespace nvcuda;
namespace wx = nvcuda::wmma;

#define NB 256
#define HD 1024
#define DD 256
#define TT 128

// ---- persistent step kernel geometry (8 warps, warp tile 32x32) ----
#define NTHR 256
#define KT2 64                    // k per chunk
#define NCH (HD / KT2)            // 16 chunks
#define LDA 72                    // A smem row stride (halves)
#define LDB 1032                  // B smem row stride (halves)
#define STGA (128 * LDA)          // halves per A stage (9216)
#define SMB_OFF (3 * STGA)
#define PERS_SMEM ((3 * STGA + 64 * LDB) * 2)   // 187392 B
#define LDG 68                    // gates smem row stride (floats); aliases A stages

// ---- fc kernel geometry ----
#define KT 32
#define NC (HD / KT)
#define LDTH 40
#define STG_A (128 * LDTH)
#define STG_B (64 * LDTH)
#define STG_H (STG_A + STG_B)
#define FC_SMEM (3 * STG_H * 2)

// ---------------- static device scratch ----------------
__device__ __half g_Wc[4096 * HD];              // gate-permuted (Wih+Whh)  8 MB
__device__ __half g_Wp[4096 * HD];              // gate-permuted Wih        8 MB
__device__ __half g_Wfc[DD * HD];
__device__ __half g_x0[NB * HD];
__device__ float  g_bp[4096];
__device__ __half g_h[(size_t)TT * NB * HD];    // hidden history fp16 (64 MB)
__device__ unsigned g_barcnt[64];               // per-half counters at [by*32]
__device__ volatile unsigned g_bargen[64];      // per-half generation at [by*32]

// fast pointwise via MUFU paths
__device__ __forceinline__ float sigm(float z) {
    return __fdividef(1.0f, 1.0f + __expf(-z));
}
__device__ __forceinline__ float ftanh(float z) {
    return __fdividef(2.0f, 1.0f + __expf(-2.0f * z)) - 1.0f;
}

#define CP16(saddr, gptr) \
    asm volatile("cp.async.cg.shared.global [%0], [%1], 16;" :: "r"(saddr), "l"(gptr) : "memory")
#define CP_COMMIT() asm volatile("cp.async.commit_group;" ::: "memory")

// barrier over the 64 CTAs sharing one batch half (single hot address per half:
// serialized atomic arrive + broadcast-friendly release — measured best (R9 vs R10/R11))
__device__ __forceinline__ void half_barrier(int by) {
    __syncthreads();
    if (threadIdx.x == 0) {
        __threadfence();
        unsigned g = g_bargen[by * 32];
        if (atomicAdd(&g_barcnt[by * 32], 1u) == 63u) {
            g_barcnt[by * 32] = 0;
            __threadfence();
            g_bargen[by * 32] = g + 1;
        } else {
            while (g_bargen[by * 32] == g) { }
        }
    }
    __syncthreads();
}

// ---------------- prep ----------------
__global__ void prep_kernel(const float* __restrict__ Wih, const float* __restrict__ Whh,
                            const float* __restrict__ bih, const float* __restrict__ bhh,
                            const float* __restrict__ Wfc, const float* __restrict__ hT) {
    size_t idx = (size_t)blockIdx.x * 256 + threadIdx.x;
    if (idx < (size_t)4096 * HD) {
        int k = (int)(idx & (HD - 1));
        int rowp = (int)(idx >> 10);            // permuted gate row: j*4 + G
        int j = rowp >> 2, G = rowp & 3;
        size_t src = (size_t)(G * HD + j) * HD + k;
        float a = Wih[src];
        g_Wp[idx] = __float2half_rn(a);
        g_Wc[idx] = __float2half_rn(a + Whh[src]);
    }
    if (idx < (size_t)DD * HD) g_Wfc[idx] = __float2half_rn(Wfc[idx]);
    if (idx < (size_t)NB * HD) g_x0[idx] = __float2half_rn(hT[idx]);
    if (idx < 4096) {
        int j = (int)(idx >> 2), G = (int)(idx & 3);
        g_bp[idx] = bih[G * HD + j] + bhh[G * HD + j];
    }
    if (idx < 64) { g_barcnt[idx] = 0u; *(unsigned*)&g_bargen[idx] = 0u; }
}

// ---------------- persistent LSTM ----------------
// grid (64, 2): n0 = bx*64 permuted gate cols (16 units), m0 = by*128 batch rows.
// 8 warps, warp tile 32x32; 3-stage cp.async pipeline; R9 atomic half-barrier.
// NEW: per-CTA rotated K-chunk order (kk = (kc + bx) & 15) so the 64 CTAs of a
// half spread over all 16 chunks of h[t-1] instead of stampeding chunk 0.
__global__ void __launch_bounds__(NTHR) lstm_persist() {
    extern __shared__ __half smh[];
    __half* smB = smh + SMB_OFF;
    float* gates = (float*)smh;                 // aliases A stages between steps

    const int tid = (int)threadIdx.x;
    const int w = tid >> 5;
    const int wm0 = (w & 3) * 32;
    const int wn0 = (w >> 2) * 32;
    const int bx = (int)blockIdx.x;
    const int by = (int)blockIdx.y;
    const size_t n0 = (size_t)bx * 64;
    const size_t m0 = (size_t)by * 128;

    const int ur = tid & 3;                     // unit quad
    const int rr = tid >> 2;                    // 0..63
    const int j0 = (int)(n0 >> 2);              // global hidden-unit base

    auto loadB = [&](const __half* __restrict__ Wsrc) {
        uint32_t sB = (uint32_t)__cvta_generic_to_shared(smB);
#pragma unroll
        for (int i = 0; i < 32; ++i) {
            int p = tid + i * NTHR;             // 0..8191
            int r = p >> 7;
            int sg = p & 127;
            CP16(sB + (uint32_t)(r * LDB + sg * 8) * 2u, Wsrc + (n0 + (size_t)r) * HD + sg * 8);
        }
        CP_COMMIT();
    };

    loadB(g_Wp);
    asm volatile("cp.async.wait_group 0;" ::: "memory");
    __syncthreads();

    float4 bq[4];
#pragma unroll
    for (int q = 0; q < 4; ++q)
        bq[q] = *(const float4*)(g_bp + n0 + (ur * 4 + q) * 4);

    float creg[8];
#pragma unroll
    for (int i = 0; i < 8; ++i) creg[i] = 0.0f;

    for (int t = 0; t < TT; ++t) {
        const __half* A = (t == 0) ? g_x0 : (g_h + (size_t)(t - 1) * NB * HD);

        // loads pipeline position kc, fetching GLOBAL chunk kk = (kc + bx) & 15
        auto loadA = [&](int kc) {
            int kk = (kc + bx) & (NCH - 1);
            uint32_t sA = (uint32_t)__cvta_generic_to_shared(smh + (kc % 3) * STGA);
            const __half* gA = A + m0 * HD + (size_t)kk * KT2;
#pragma unroll
            for (int i = 0; i < 4; ++i) {
                int p = tid + i * NTHR;         // 0..1023
                int r = p >> 3;
                int sg = p & 7;
                CP16(sA + (uint32_t)(r * LDA + sg * 8) * 2u, gA + (size_t)r * HD + sg * 8);
            }
            CP_COMMIT();
        };

        wx::fragment<wx::accumulator, 16, 16, 16, float> cf[2][2];
#pragma unroll
        for (int i = 0; i < 2; ++i)
#pragma unroll
            for (int j = 0; j < 2; ++j) wx::fill_fragment(cf[i][j], 0.0f);

        loadA(0);
        loadA(1);

        for (int kc = 0; kc < NCH; ++kc) {
            if (kc < NCH - 1) asm volatile("cp.async.wait_group 1;" ::: "memory");
            else              asm volatile("cp.async.wait_group 0;" ::: "memory");
            __syncthreads();
            if (kc + 2 < NCH) loadA(kc + 2);

            const int kk = (kc + bx) & (NCH - 1);          // global chunk in this stage
            const __half* smA = smh + (kc % 3) * STGA;
#pragma unroll
            for (int ks = 0; ks < 4; ++ks) {
                wx::fragment<wx::matrix_a, 16, 16, 16, __half, wx::row_major> af[2];
                wx::fragment<wx::matrix_b, 16, 16, 16, __half, wx::col_major> bf[2];
#pragma unroll
                for (int i = 0; i < 2; ++i)
                    wx::load_matrix_sync(af[i], smA + (wm0 + i * 16) * LDA + ks * 16, LDA);
#pragma unroll
                for (int j = 0; j < 2; ++j)
                    wx::load_matrix_sync(bf[j], smB + (wn0 + j * 16) * LDB + kk * KT2 + ks * 16, LDB);
#pragma unroll
                for (int i = 0; i < 2; ++i)
#pragma unroll
                    for (int j = 0; j < 2; ++j)
                        wx::mma_sync(cf[i][j], af[i], bf[j], cf[i][j]);
            }
        }

        __syncthreads();     // A stages free; alias as gates
#pragma unroll
        for (int i = 0; i < 2; ++i)
#pragma unroll
            for (int j = 0; j < 2; ++j)
                wx::store_matrix_sync(gates + (wm0 + i * 16) * LDG + wn0 + j * 16,
                                      cf[i][j], LDG, wx::mem_row_major);
        __syncthreads();

        // swap in combined weights after step 0 (overlaps epilogue)
        if (t == 0) loadB(g_Wc);

        // pointwise epilogue; c stays in registers
        __half* hbase = g_h + (size_t)t * NB * HD;
#pragma unroll
        for (int p = 0; p < 2; ++p) {
            int r = rr + p * 64;
            size_t m = m0 + r;
            __half hv[4];
#pragma unroll
            for (int q = 0; q < 4; ++q) {
                float4 gv = *(const float4*)(gates + r * LDG + (ur * 4 + q) * 4);
                const float* bb = &bq[q].x;
                float iv = sigm(gv.x + bb[0]);
                float fv = sigm(gv.y + bb[1]);
                float gg = ftanh(gv.z + bb[2]);
                float ov = sigm(gv.w + bb[3]);
                float c = fmaf(fv, creg[p * 4 + q], iv * gg);
                creg[p * 4 + q] = c;
                hv[q] = __float2half_rn(ov * ftanh(c));
            }
            *(uint2*)(hbase + m * HD + j0 + ur * 4) = *(uint2*)hv;
        }

        if (t == 0) asm volatile("cp.async.wait_group 0;" ::: "memory");  // retire B swap

        half_barrier(by);    // h[t] of this batch half visible to its 64 CTAs
    }
}

// ---------------- FC: out[32768,256] = h @ Wfc^T + b ----------------
__device__ __forceinline__ void gemm16_fc(const __half* __restrict__ A, size_t m0,
                                          const __half* __restrict__ B, size_t n0,
                                          __half* smh, float* gates) {
    const int tid = (int)threadIdx.x;
    const int w = tid >> 5;
    const int wm0 = (w & 3) * 32;
    const int wn0 = (w >> 2) * 32;

    wx::fragment<wx::accumulator, 16, 16, 16, float> cf[2][2];
#pragma unroll
    for (int i = 0; i < 2; ++i)
#pragma unroll
        for (int j = 0; j < 2; ++j) wx::fill_fragment(cf[i][j], 0.0f);

    auto load_chunk = [&](int kc) {
        __half* smA = smh + (kc % 3) * STG_H;
        __half* smB = smA + STG_A;
        uint32_t sA = (uint32_t)__cvta_generic_to_shared(smA);
        uint32_t sB = (uint32_t)__cvta_generic_to_shared(smB);
        const __half* gA = A + m0 * HD + (size_t)kc * KT;
        const __half* gB = B + n0 * HD + (size_t)kc * KT;
#pragma unroll
        for (int i = 0; i < 2; ++i) {
            int p = tid + i * 256;
            int r = p >> 2, seg = p & 3;
            CP16(sA + (uint32_t)(r * LDTH + seg * 8) * 2u, gA + (size_t)r * HD + seg * 8);
        }
        {
            int r = tid >> 2, seg = tid & 3;
            CP16(sB + (uint32_t)(r * LDTH + seg * 8) * 2u, gB + (size_t)r * HD + seg * 8);
        }
        CP_COMMIT();
    };

    load_chunk(0);
    load_chunk(1);

    for (int kc = 0; kc < NC; ++kc) {
        if (kc < NC - 1) asm volatile("cp.async.wait_group 1;" ::: "memory");
        else             asm volatile("cp.async.wait_group 0;" ::: "memory");
        __syncthreads();
        if (kc + 2 < NC) load_chunk(kc + 2);

        __half* smA = smh + (kc % 3) * STG_H;
        __half* smB = smA + STG_A;
#pragma unroll
        for (int ks = 0; ks < 2; ++ks) {
            wx::fragment<wx::matrix_a, 16, 16, 16, __half, wx::row_major> af[2];
            wx::fragment<wx::matrix_b, 16, 16, 16, __half, wx::col_major> bf[2];
#pragma unroll
            for (int i = 0; i < 2; ++i)
                wx::load_matrix_sync(af[i], smA + (wm0 + i * 16) * LDTH + ks * 16, LDTH);
#pragma unroll
            for (int j = 0; j < 2; ++j)
                wx::load_matrix_sync(bf[j], smB + (wn0 + j * 16) * LDTH + ks * 16, LDTH);
#pragma unroll
            for (int i = 0; i < 2; ++i)
#pragma unroll
                for (int j = 0; j < 2; ++j)
                    wx::mma_sync(cf[i][j], af[i], bf[j], cf[i][j]);
        }
    }

    __syncthreads();
#pragma unroll
    for (int i = 0; i < 2; ++i)
#pragma unroll
        for (int j = 0; j < 2; ++j)
            wx::store_matrix_sync(gates + (wm0 + i * 16) * LDG + wn0 + j * 16,
                                  cf[i][j], LDG, wx::mem_row_major);
    __syncthreads();
}

__global__ void __launch_bounds__(256) fc_kernel(const float* __restrict__ bfc,
                                                 float* __restrict__ out) {
    extern __shared__ __half smh[];
    float* gates = (float*)smh;
    size_t n0 = (size_t)blockIdx.x * 64;
    size_t m0 = (size_t)blockIdx.y * 128;

    gemm16_fc(g_h, m0, g_Wfc, n0, smh, gates);

    const int tid = (int)threadIdx.x;
    const int cg = tid & 3;
    const int rr = tid >> 2;
#pragma unroll
    for (int p = 0; p < 2; ++p) {
        int r = rr + p * 64;
        size_t m = m0 + r;
#pragma unroll
        for (int q = 0; q < 4; ++q) {
            int c = cg * 16 + q * 4;
            float4 gv = *(const float4*)(gates + r * LDG + c);
            float4 bv = *(const float4*)(bfc + n0 + c);
            gv.x += bv.x; gv.y += bv.y; gv.z += bv.z; gv.w += bv.w;
            *(float4*)(out + m * DD + n0 + c) = gv;
        }
    }
}

// ---------------- launch ----------------
extern "C" void kernel_launch(void* const* d_in, const int* in_sizes, int n_in,
                              void* d_out, int out_size) {
    const float* hT  = (const float*)d_in[0];
    // d_in[1] = t (int32) — fixed 128 for this problem
    const float* Wih = (const float*)d_in[2];
    const float* Whh = (const float*)d_in[3];
    const float* bih = (const float*)d_in[4];
    const float* bhh = (const float*)d_in[5];
    const float* Wfc = (const float*)d_in[6];
    const float* bfc = (const float*)d_in[7];
    float* out = (float*)d_out;

    cudaFuncSetAttribute(lstm_persist, cudaFuncAttributeMaxDynamicSharedMemorySize, PERS_SMEM);
    cudaFuncSetAttribute(fc_kernel, cudaFuncAttributeMaxDynamicSharedMemorySize, FC_SMEM);

    prep_kernel<<<(4096 * HD) / 256, 256>>>(Wih, Whh, bih, bhh, Wfc, hT);

    lstm_persist<<<dim3(64, 2), NTHR, PERS_SMEM>>>();

    fc_kernel<<<dim3(4, 256), 256, FC_SMEM>>>(bfc, out);
}

// round 13
// speedup vs baseline: 1.2515x; 1.0633x over previous
#include <cuda_runtime.h>
#include <cuda_fp16.h>
#include <mma.h>
#include <cstdint>
#include <cstddef>

using namespace nvcuda;
namespace wx = nvcuda::wmma;

#define NB 256
#define HD 1024
#define DD 256
#define TT 128

// ---- persistent step kernel geometry (8 warps, warp tile 32x32) ----
#define NTHR 256
#define KT2 64                    // k per chunk
#define NCH (HD / KT2)            // 16 chunks
#define LDA 72                    // A smem row stride (halves)
#define LDB 1032                  // B smem row stride (halves)
#define STGA (128 * LDA)          // halves per A stage (9216)
#define SMB_OFF (3 * STGA)
#define PERS_SMEM ((3 * STGA + 64 * LDB) * 2)   // 187392 B

// ---- fc kernel geometry ----
#define KT 32
#define NC (HD / KT)
#define LDTH 40
#define LDG 68
#define STG_A (128 * LDTH)
#define STG_B (64 * LDTH)
#define STG_H (STG_A + STG_B)
#define FC_SMEM (3 * STG_H * 2)

// ---------------- static device scratch ----------------
__device__ __half g_Wc[4096 * HD];              // gate-permuted (Wih+Whh)  8 MB
__device__ __half g_Wp[4096 * HD];              // gate-permuted Wih        8 MB
__device__ __half g_Wfc[DD * HD];
__device__ __half g_x0[NB * HD];
__device__ float  g_bp[4096];
__device__ __half g_h[(size_t)TT * NB * HD];    // hidden history fp16 (64 MB)
__device__ unsigned g_barcnt[64];               // per-half counters at [by*32]
__device__ volatile unsigned g_bargen[64];      // per-half generation at [by*32]

// fast pointwise via MUFU paths
__device__ __forceinline__ float sigm(float z) {
    return __fdividef(1.0f, 1.0f + __expf(-z));
}
__device__ __forceinline__ float ftanh(float z) {
    return __fdividef(2.0f, 1.0f + __expf(-2.0f * z)) - 1.0f;
}

#define CP16(saddr, gptr) \
    asm volatile("cp.async.cg.shared.global [%0], [%1], 16;" :: "r"(saddr), "l"(gptr) : "memory")
#define CP_COMMIT() asm volatile("cp.async.commit_group;" ::: "memory")

// barrier over the 64 CTAs sharing one batch half (R9-proven design)
__device__ __forceinline__ void half_barrier(int by) {
    __syncthreads();
    if (threadIdx.x == 0) {
        __threadfence();
        unsigned g = g_bargen[by * 32];
        if (atomicAdd(&g_barcnt[by * 32], 1u) == 63u) {
            g_barcnt[by * 32] = 0;
            __threadfence();
            g_bargen[by * 32] = g + 1;
        } else {
            while (g_bargen[by * 32] == g) { }
        }
    }
    __syncthreads();
}

// ---------------- prep ----------------
// New gate permutation matched to the mma accumulator layout:
// within each 16-col group (4 units), unit u: i->2u, f->2u+1, g->8+2u, o->9+2u.
// Inverse (from permuted row rowp): group=rowp>>4, w16=rowp&15,
//   G = ((w16>>3)<<1) | (w16&1),  u = (w16&7)>>1,  j = group*4 + u.
__global__ void prep_kernel(const float* __restrict__ Wih, const float* __restrict__ Whh,
                            const float* __restrict__ bih, const float* __restrict__ bhh,
                            const float* __restrict__ Wfc, const float* __restrict__ hT) {
    size_t idx = (size_t)blockIdx.x * 256 + threadIdx.x;
    if (idx < (size_t)4096 * HD) {
        int k = (int)(idx & (HD - 1));
        int rowp = (int)(idx >> 10);
        int w16 = rowp & 15;
        int G = ((w16 >> 3) << 1) | (w16 & 1);
        int j = (rowp >> 4) * 4 + ((w16 & 7) >> 1);
        size_t src = (size_t)(G * HD + j) * HD + k;
        float a = Wih[src];
        g_Wp[idx] = __float2half_rn(a);
        g_Wc[idx] = __float2half_rn(a + Whh[src]);
    }
    if (idx < (size_t)DD * HD) g_Wfc[idx] = __float2half_rn(Wfc[idx]);
    if (idx < (size_t)NB * HD) g_x0[idx] = __float2half_rn(hT[idx]);
    if (idx < 4096) {
        int w16 = (int)(idx & 15);
        int G = ((w16 >> 3) << 1) | (w16 & 1);
        int j = ((int)(idx >> 4)) * 4 + ((w16 & 7) >> 1);
        g_bp[idx] = bih[G * HD + j] + bhh[G * HD + j];
    }
    if (idx < 64) { g_barcnt[idx] = 0u; *(unsigned*)&g_bargen[idx] = 0u; }
}

// ---------------- persistent LSTM ----------------
// grid (64, 2): n0 = bx*64 permuted gate cols (16 units), m0 = by*128 batch rows.
// 8 warps, warp tile 32x32; 3-stage cp.async pipeline; R9 atomic half-barrier.
// NEW: pointwise epilogue computed directly from accumulator fragments (no gates
// smem roundtrip); h staged through a 4KB smem buffer for coalesced stores.
__global__ void __launch_bounds__(NTHR) lstm_persist() {
    extern __shared__ __half smh[];
    __half* smB = smh + SMB_OFF;
    __half* hst = smh;                          // 128x16 halves staging (aliases stage 0)

    const int tid = (int)threadIdx.x;
    const int w = tid >> 5;
    const int lane = tid & 31;
    const int wm0 = (w & 3) * 32;
    const int wn0 = (w >> 2) * 32;
    const int fr = lane >> 2;                   // fragment row 0..7
    const int cq = lane & 3;                    // fragment col quad
    const int bx = (int)blockIdx.x;
    const int by = (int)blockIdx.y;
    const size_t n0 = (size_t)bx * 64;
    const size_t m0 = (size_t)by * 128;

    auto loadB = [&](const __half* __restrict__ Wsrc) {
        uint32_t sB = (uint32_t)__cvta_generic_to_shared(smB);
#pragma unroll
        for (int i = 0; i < 32; ++i) {
            int p = tid + i * NTHR;             // 0..8191
            int r = p >> 7;
            int sg = p & 127;
            CP16(sB + (uint32_t)(r * LDB + sg * 8) * 2u, Wsrc + (n0 + (size_t)r) * HD + sg * 8);
        }
        CP_COMMIT();
    };

    loadB(g_Wp);
    asm volatile("cp.async.wait_group 0;" ::: "memory");
    __syncthreads();

    // per-thread biases: unit ul[j], gates (i,f) at cols 2cq,2cq+1 and (g,o) at 8+2cq,9+2cq
    float2 bif[2], bgo[2];
    int ul[2];
#pragma unroll
    for (int j = 0; j < 2; ++j) {
        bif[j] = *(const float2*)(g_bp + n0 + wn0 + 16 * j + 2 * cq);
        bgo[j] = *(const float2*)(g_bp + n0 + wn0 + 16 * j + 8 + 2 * cq);
        ul[j] = ((wn0 + 16 * j) >> 4) * 4 + cq;
    }

    float creg[8];                              // [i][rowhalf][j] -> i*4 + rh*2 + j
#pragma unroll
    for (int i = 0; i < 8; ++i) creg[i] = 0.0f;

    for (int t = 0; t < TT; ++t) {
        const __half* A = (t == 0) ? g_x0 : (g_h + (size_t)(t - 1) * NB * HD);

        auto loadA = [&](int kc) {
            uint32_t sA = (uint32_t)__cvta_generic_to_shared(smh + (kc % 3) * STGA);
            const __half* gA = A + m0 * HD + (size_t)kc * KT2;
#pragma unroll
            for (int i = 0; i < 4; ++i) {
                int p = tid + i * NTHR;         // 0..1023
                int r = p >> 3;
                int sg = p & 7;
                CP16(sA + (uint32_t)(r * LDA + sg * 8) * 2u, gA + (size_t)r * HD + sg * 8);
            }
            CP_COMMIT();
        };

        wx::fragment<wx::accumulator, 16, 16, 16, float> cf[2][2];
#pragma unroll
        for (int i = 0; i < 2; ++i)
#pragma unroll
            for (int j = 0; j < 2; ++j) wx::fill_fragment(cf[i][j], 0.0f);

        loadA(0);
        loadA(1);

        for (int kc = 0; kc < NCH; ++kc) {
            if (kc < NCH - 1) asm volatile("cp.async.wait_group 1;" ::: "memory");
            else              asm volatile("cp.async.wait_group 0;" ::: "memory");
            __syncthreads();
            if (kc + 2 < NCH) loadA(kc + 2);

            const __half* smA = smh + (kc % 3) * STGA;
#pragma unroll
            for (int ks = 0; ks < 4; ++ks) {
                wx::fragment<wx::matrix_a, 16, 16, 16, __half, wx::row_major> af[2];
                wx::fragment<wx::matrix_b, 16, 16, 16, __half, wx::col_major> bf[2];
#pragma unroll
                for (int i = 0; i < 2; ++i)
                    wx::load_matrix_sync(af[i], smA + (wm0 + i * 16) * LDA + ks * 16, LDA);
#pragma unroll
                for (int j = 0; j < 2; ++j)
                    wx::load_matrix_sync(bf[j], smB + (wn0 + j * 16) * LDB + kc * KT2 + ks * 16, LDB);
#pragma unroll
                for (int i = 0; i < 2; ++i)
#pragma unroll
                    for (int j = 0; j < 2; ++j)
                        wx::mma_sync(cf[i][j], af[i], bf[j], cf[i][j]);
            }
        }

        __syncthreads();      // all ldsm done; stage 0 free for h staging

        // swap in combined weights after step 0 (overlaps register epilogue)
        if (t == 0) loadB(g_Wc);

        // ---- register epilogue ----
        // Accumulator layout (two concatenated m16n8k16 tiles, PTX-documented):
        //  x0,x1 = (row fr,   cols 2cq,2cq+1)   -> gates i,f of unit ul[j]
        //  x2,x3 = (row fr+8, cols 2cq,2cq+1)   -> gates i,f
        //  x4,x5 = (row fr,   cols 8+2cq,9+2cq) -> gates g,o
        //  x6,x7 = (row fr+8, cols 8+2cq,9+2cq) -> gates g,o
#pragma unroll
        for (int i = 0; i < 2; ++i) {
            int rA = wm0 + 16 * i + fr;
#pragma unroll
            for (int j = 0; j < 2; ++j) {
                const float* x = cf[i][j].x;
                float bi = bif[j].x, bfv = bif[j].y, bg = bgo[j].x, bo = bgo[j].y;
                {   // row rA
                    float iv = sigm(x[0] + bi);
                    float fv = sigm(x[1] + bfv);
                    float gg = ftanh(x[4] + bg);
                    float ov = sigm(x[5] + bo);
                    float c = fmaf(fv, creg[i * 4 + j], iv * gg);
                    creg[i * 4 + j] = c;
                    hst[rA * 16 + ul[j]] = __float2half_rn(ov * ftanh(c));
                }
                {   // row rA + 8
                    float iv = sigm(x[2] + bi);
                    float fv = sigm(x[3] + bfv);
                    float gg = ftanh(x[6] + bg);
                    float ov = sigm(x[7] + bo);
                    float c = fmaf(fv, creg[i * 4 + 2 + j], iv * gg);
                    creg[i * 4 + 2 + j] = c;
                    hst[(rA + 8) * 16 + ul[j]] = __float2half_rn(ov * ftanh(c));
                }
            }
        }

        if (t == 0) asm volatile("cp.async.wait_group 0;" ::: "memory");  // retire B swap
        __syncthreads();      // staging complete

        // coalesced h store: 128 rows x 16 halves (32B/row), 2 threads per row
        {
            int row = tid >> 1, hf = tid & 1;
            uint4 v = *(const uint4*)((const char*)hst + row * 32 + hf * 16);
            __half* hbase = g_h + (size_t)t * NB * HD;
            *(uint4*)(hbase + (m0 + (size_t)row) * HD + bx * 16 + hf * 8) = v;
        }

        half_barrier(by);     // h[t] of this batch half visible to its 64 CTAs
    }
}

// ---------------- FC: out[32768,256] = h @ Wfc^T + b (unchanged R9 path) ----------
__device__ __forceinline__ void gemm16_fc(const __half* __restrict__ A, size_t m0,
                                          const __half* __restrict__ B, size_t n0,
                                          __half* smh, float* gates) {
    const int tid = (int)threadIdx.x;
    const int w = tid >> 5;
    const int wm0 = (w & 3) * 32;
    const int wn0 = (w >> 2) * 32;

    wx::fragment<wx::accumulator, 16, 16, 16, float> cf[2][2];
#pragma unroll
    for (int i = 0; i < 2; ++i)
#pragma unroll
        for (int j = 0; j < 2; ++j) wx::fill_fragment(cf[i][j], 0.0f);

    auto load_chunk = [&](int kc) {
        __half* smA = smh + (kc % 3) * STG_H;
        __half* smB = smA + STG_A;
        uint32_t sA = (uint32_t)__cvta_generic_to_shared(smA);
        uint32_t sB = (uint32_t)__cvta_generic_to_shared(smB);
        const __half* gA = A + m0 * HD + (size_t)kc * KT;
        const __half* gB = B + n0 * HD + (size_t)kc * KT;
#pragma unroll
        for (int i = 0; i < 2; ++i) {
            int p = tid + i * 256;
            int r = p >> 2, seg = p & 3;
            CP16(sA + (uint32_t)(r * LDTH + seg * 8) * 2u, gA + (size_t)r * HD + seg * 8);
        }
        {
            int r = tid >> 2, seg = tid & 3;
            CP16(sB + (uint32_t)(r * LDTH + seg * 8) * 2u, gB + (size_t)r * HD + seg * 8);
        }
        CP_COMMIT();
    };

    load_chunk(0);
    load_chunk(1);

    for (int kc = 0; kc < NC; ++kc) {
        if (kc < NC - 1) asm volatile("cp.async.wait_group 1;" ::: "memory");
        else             asm volatile("cp.async.wait_group 0;" ::: "memory");
        __syncthreads();
        if (kc + 2 < NC) load_chunk(kc + 2);

        __half* smA = smh + (kc % 3) * STG_H;
        __half* smB = smA + STG_A;
#pragma unroll
        for (int ks = 0; ks < 2; ++ks) {
            wx::fragment<wx::matrix_a, 16, 16, 16, __half, wx::row_major> af[2];
            wx::fragment<wx::matrix_b, 16, 16, 16, __half, wx::col_major> bf[2];
#pragma unroll
            for (int i = 0; i < 2; ++i)
                wx::load_matrix_sync(af[i], smA + (wm0 + i * 16) * LDTH + ks * 16, LDTH);
#pragma unroll
            for (int j = 0; j < 2; ++j)
                wx::load_matrix_sync(bf[j], smB + (wn0 + j * 16) * LDTH + ks * 16, LDTH);
#pragma unroll
            for (int i = 0; i < 2; ++i)
#pragma unroll
                for (int j = 0; j < 2; ++j)
                    wx::mma_sync(cf[i][j], af[i], bf[j], cf[i][j]);
        }
    }

    __syncthreads();
#pragma unroll
    for (int i = 0; i < 2; ++i)
#pragma unroll
        for (int j = 0; j < 2; ++j)
            wx::store_matrix_sync(gates + (wm0 + i * 16) * LDG + wn0 + j * 16,
                                  cf[i][j], LDG, wx::mem_row_major);
    __syncthreads();
}

__global__ void __launch_bounds__(256) fc_kernel(const float* __restrict__ bfc,
                                                 float* __restrict__ out) {
    extern __shared__ __half smh[];
    float* gates = (float*)smh;
    size_t n0 = (size_t)blockIdx.x * 64;
    size_t m0 = (size_t)blockIdx.y * 128;

    gemm16_fc(g_h, m0, g_Wfc, n0, smh, gates);

    const int tid = (int)threadIdx.x;
    const int cg = tid & 3;
    const int rr = tid >> 2;
#pragma unroll
    for (int p = 0; p < 2; ++p) {
        int r = rr + p * 64;
        size_t m = m0 + r;
#pragma unroll
        for (int q = 0; q < 4; ++q) {
            int c = cg * 16 + q * 4;
            float4 gv = *(const float4*)(gates + r * LDG + c);
            float4 bv = *(const float4*)(bfc + n0 + c);
            gv.x += bv.x; gv.y += bv.y; gv.z += bv.z; gv.w += bv.w;
            *(float4*)(out + m * DD + n0 + c) = gv;
        }
    }
}

// ---------------- launch ----------------
extern "C" void kernel_launch(void* const* d_in, const int* in_sizes, int n_in,
                              void* d_out, int out_size) {
    const float* hT  = (const float*)d_in[0];
    // d_in[1] = t (int32) — fixed 128 for this problem
    const float* Wih = (const float*)d_in[2];
    const float* Whh = (const float*)d_in[3];
    const float* bih = (const float*)d_in[4];
    const float* bhh = (const float*)d_in[5];
    const float* Wfc = (const float*)d_in[6];
    const float* bfc = (const float*)d_in[7];
    float* out = (float*)d_out;

    cudaFuncSetAttribute(lstm_persist, cudaFuncAttributeMaxDynamicSharedMemorySize, PERS_SMEM);
    cudaFuncSetAttribute(fc_kernel, cudaFuncAttributeMaxDynamicSharedMemorySize, FC_SMEM);

    prep_kernel<<<(4096 * HD) / 256, 256>>>(Wih, Whh, bih, bhh, Wfc, hT);

    lstm_persist<<<dim3(64, 2), NTHR, PERS_SMEM>>>();

    fc_kernel<<<dim3(4, 256), 256, FC_SMEM>>>(bfc, out);
}

// round 16
// speedup vs baseline: 1.2783x; 1.0214x over previous
#include <cuda_runtime.h>
#include <cuda_fp16.h>
#include <mma.h>
#include <cstdint>
#include <cstddef>

using namespace nvcuda;
namespace wx = nvcuda::wmma;

#define NB 256
#define HD 1024
#define DD 256
#define TT 128

// ---- persistent step kernel geometry (8 warps, warp tile 32x32, 4-stage pipe) ----
#define NTHR 256
#define KT2 64                    // k per chunk
#define NCH (HD / KT2)            // 16 chunks
#define NSTG 4                    // pipeline stages
#define LDA 72                    // A smem row stride (halves)
#define LDB 1032                  // B smem row stride (halves)
#define STGA (128 * LDA)          // halves per A stage (9216)
#define SMB_OFF (NSTG * STGA)
#define PERS_SMEM ((NSTG * STGA + 64 * LDB) * 2)   // 205824 B

// ---- fc kernel geometry ----
#define KT 32
#define NC (HD / KT)
#define LDTH 40
#define LDG 68
#define STG_A (128 * LDTH)
#define STG_B (64 * LDTH)
#define STG_H (STG_A + STG_B)
#define FC_SMEM (3 * STG_H * 2)

// ---------------- static device scratch ----------------
__device__ __half g_Wc[4096 * HD];              // gate-permuted (Wih+Whh)  8 MB
__device__ __half g_Wp[4096 * HD];              // gate-permuted Wih        8 MB
__device__ __half g_Wfc[DD * HD];
__device__ __half g_x0[NB * HD];
__device__ float  g_bp[4096];
__device__ __half g_h[(size_t)TT * NB * HD];    // hidden history fp16 (64 MB)
__device__ unsigned g_barcnt[64];               // per-half counters at [by*32]
__device__ volatile unsigned g_bargen[64];      // per-half generation at [by*32]

// fast pointwise via MUFU paths
__device__ __forceinline__ float sigm(float z) {
    return __fdividef(1.0f, 1.0f + __expf(-z));
}
__device__ __forceinline__ float ftanh(float z) {
    return __fdividef(2.0f, 1.0f + __expf(-2.0f * z)) - 1.0f;
}

#define CP16(saddr, gptr) \
    asm volatile("cp.async.cg.shared.global [%0], [%1], 16;" :: "r"(saddr), "l"(gptr) : "memory")
#define CP_COMMIT() asm volatile("cp.async.commit_group;" ::: "memory")

// barrier over the 64 CTAs sharing one batch half (R9/R13-proven design)
__device__ __forceinline__ void half_barrier(int by) {
    __syncthreads();
    if (threadIdx.x == 0) {
        __threadfence();
        unsigned g = g_bargen[by * 32];
        if (atomicAdd(&g_barcnt[by * 32], 1u) == 63u) {
            g_barcnt[by * 32] = 0;
            __threadfence();
            g_bargen[by * 32] = g + 1;
        } else {
            while (g_bargen[by * 32] == g) { }
        }
    }
    __syncthreads();
}

// ---------------- prep ----------------
// Gate permutation matched to the mma accumulator layout (R13-proven):
// rowp: group=rowp>>4, w16=rowp&15 -> G=((w16>>3)<<1)|(w16&1), j=group*4+((w16&7)>>1)
__global__ void prep_kernel(const float* __restrict__ Wih, const float* __restrict__ Whh,
                            const float* __restrict__ bih, const float* __restrict__ bhh,
                            const float* __restrict__ Wfc, const float* __restrict__ hT) {
    size_t idx = (size_t)blockIdx.x * 256 + threadIdx.x;
    if (idx < (size_t)4096 * HD) {
        int k = (int)(idx & (HD - 1));
        int rowp = (int)(idx >> 10);
        int w16 = rowp & 15;
        int G = ((w16 >> 3) << 1) | (w16 & 1);
        int j = (rowp >> 4) * 4 + ((w16 & 7) >> 1);
        size_t src = (size_t)(G * HD + j) * HD + k;
        float a = Wih[src];
        g_Wp[idx] = __float2half_rn(a);
        g_Wc[idx] = __float2half_rn(a + Whh[src]);
    }
    if (idx < (size_t)DD * HD) g_Wfc[idx] = __float2half_rn(Wfc[idx]);
    if (idx < (size_t)NB * HD) g_x0[idx] = __float2half_rn(hT[idx]);
    if (idx < 4096) {
        int w16 = (int)(idx & 15);
        int G = ((w16 >> 3) << 1) | (w16 & 1);
        int j = ((int)(idx >> 4)) * 4 + ((w16 & 7) >> 1);
        g_bp[idx] = bih[G * HD + j] + bhh[G * HD + j];
    }
    if (idx < 64) { g_barcnt[idx] = 0u; *(unsigned*)&g_bargen[idx] = 0u; }
}

// ---------------- persistent LSTM ----------------
// grid (64, 2): n0 = bx*64 permuted gate cols (16 units), m0 = by*128 batch rows.
// 8 warps, warp tile 32x32; 4-stage cp.async pipeline (wait_group 2 slack);
// R9 atomic half-barrier; R13 register epilogue.
__global__ void __launch_bounds__(NTHR) lstm_persist() {
    extern __shared__ __half smh[];
    __half* smB = smh + SMB_OFF;
    __half* hst = smh;                          // 128x16 halves staging (aliases stage 0)

    const int tid = (int)threadIdx.x;
    const int w = tid >> 5;
    const int lane = tid & 31;
    const int wm0 = (w & 3) * 32;
    const int wn0 = (w >> 2) * 32;
    const int fr = lane >> 2;                   // fragment row 0..7
    const int cq = lane & 3;                    // fragment col quad
    const int bx = (int)blockIdx.x;
    const int by = (int)blockIdx.y;
    const size_t n0 = (size_t)bx * 64;
    const size_t m0 = (size_t)by * 128;

    auto loadB = [&](const __half* __restrict__ Wsrc) {
        uint32_t sB = (uint32_t)__cvta_generic_to_shared(smB);
#pragma unroll
        for (int i = 0; i < 32; ++i) {
            int p = tid + i * NTHR;             // 0..8191
            int r = p >> 7;
            int sg = p & 127;
            CP16(sB + (uint32_t)(r * LDB + sg * 8) * 2u, Wsrc + (n0 + (size_t)r) * HD + sg * 8);
        }
        CP_COMMIT();
    };

    loadB(g_Wp);
    asm volatile("cp.async.wait_group 0;" ::: "memory");
    __syncthreads();

    float2 bif[2], bgo[2];
    int ul[2];
#pragma unroll
    for (int j = 0; j < 2; ++j) {
        bif[j] = *(const float2*)(g_bp + n0 + wn0 + 16 * j + 2 * cq);
        bgo[j] = *(const float2*)(g_bp + n0 + wn0 + 16 * j + 8 + 2 * cq);
        ul[j] = ((wn0 + 16 * j) >> 4) * 4 + cq;
    }

    float creg[8];
#pragma unroll
    for (int i = 0; i < 8; ++i) creg[i] = 0.0f;

    for (int t = 0; t < TT; ++t) {
        const __half* A = (t == 0) ? g_x0 : (g_h + (size_t)(t - 1) * NB * HD);

        auto loadA = [&](int kc) {
            uint32_t sA = (uint32_t)__cvta_generic_to_shared(smh + (kc % NSTG) * STGA);
            const __half* gA = A + m0 * HD + (size_t)kc * KT2;
#pragma unroll
            for (int i = 0; i < 4; ++i) {
                int p = tid + i * NTHR;         // 0..1023
                int r = p >> 3;
                int sg = p & 7;
                CP16(sA + (uint32_t)(r * LDA + sg * 8) * 2u, gA + (size_t)r * HD + sg * 8);
            }
            CP_COMMIT();
        };

        wx::fragment<wx::accumulator, 16, 16, 16, float> cf[2][2];
#pragma unroll
        for (int i = 0; i < 2; ++i)
#pragma unroll
            for (int j = 0; j < 2; ++j) wx::fill_fragment(cf[i][j], 0.0f);

        loadA(0);
        loadA(1);
        loadA(2);

        for (int kc = 0; kc < NCH; ++kc) {
            if (kc < NCH - 2)      asm volatile("cp.async.wait_group 2;" ::: "memory");
            else if (kc < NCH - 1) asm volatile("cp.async.wait_group 1;" ::: "memory");
            else                   asm volatile("cp.async.wait_group 0;" ::: "memory");
            __syncthreads();
            if (kc + 3 < NCH) loadA(kc + 3);    // overwrites stage consumed last iter

            const __half* smA = smh + (kc % NSTG) * STGA;
#pragma unroll
            for (int ks = 0; ks < 4; ++ks) {
                wx::fragment<wx::matrix_a, 16, 16, 16, __half, wx::row_major> af[2];
                wx::fragment<wx::matrix_b, 16, 16, 16, __half, wx::col_major> bf[2];
#pragma unroll
                for (int i = 0; i < 2; ++i)
                    wx::load_matrix_sync(af[i], smA + (wm0 + i * 16) * LDA + ks * 16, LDA);
#pragma unroll
                for (int j = 0; j < 2; ++j)
                    wx::load_matrix_sync(bf[j], smB + (wn0 + j * 16) * LDB + kc * KT2 + ks * 16, LDB);
#pragma unroll
                for (int i = 0; i < 2; ++i)
#pragma unroll
                    for (int j = 0; j < 2; ++j)
                        wx::mma_sync(cf[i][j], af[i], bf[j], cf[i][j]);
            }
        }

        __syncthreads();      // all ldsm done; stage 0 free for h staging

        // swap in combined weights after step 0 (overlaps register epilogue)
        if (t == 0) loadB(g_Wc);

        // ---- register epilogue (R13-proven accumulator layout) ----
#pragma unroll
        for (int i = 0; i < 2; ++i) {
            int rA = wm0 + 16 * i + fr;
#pragma unroll
            for (int j = 0; j < 2; ++j) {
                const float* x = cf[i][j].x;
                float bi = bif[j].x, bfv = bif[j].y, bg = bgo[j].x, bo = bgo[j].y;
                {   // row rA
                    float iv = sigm(x[0] + bi);
                    float fv = sigm(x[1] + bfv);
                    float gg = ftanh(x[4] + bg);
                    float ov = sigm(x[5] + bo);
                    float c = fmaf(fv, creg[i * 4 + j], iv * gg);
                    creg[i * 4 + j] = c;
                    hst[rA * 16 + ul[j]] = __float2half_rn(ov * ftanh(c));
                }
                {   // row rA + 8
                    float iv = sigm(x[2] + bi);
                    float fv = sigm(x[3] + bfv);
                    float gg = ftanh(x[6] + bg);
                    float ov = sigm(x[7] + bo);
                    float c = fmaf(fv, creg[i * 4 + 2 + j], iv * gg);
                    creg[i * 4 + 2 + j] = c;
                    hst[(rA + 8) * 16 + ul[j]] = __float2half_rn(ov * ftanh(c));
                }
            }
        }

        if (t == 0) asm volatile("cp.async.wait_group 0;" ::: "memory");  // retire B swap
        __syncthreads();      // staging complete

        // coalesced h store: 128 rows x 32B, 2 threads per row
        {
            int row = tid >> 1, hf = tid & 1;
            uint4 v = *(const uint4*)((const char*)hst + row * 32 + hf * 16);
            __half* hbase = g_h + (size_t)t * NB * HD;
            *(uint4*)(hbase + (m0 + (size_t)row) * HD + bx * 16 + hf * 8) = v;
        }

        half_barrier(by);     // h[t] of this batch half visible to its 64 CTAs
    }
}

// ---------------- FC: out[32768,256] = h @ Wfc^T + b (unchanged) ----------
__device__ __forceinline__ void gemm16_fc(const __half* __restrict__ A, size_t m0,
                                          const __half* __restrict__ B, size_t n0,
                                          __half* smh, float* gates) {
    const int tid = (int)threadIdx.x;
    const int w = tid >> 5;
    const int wm0 = (w & 3) * 32;
    const int wn0 = (w >> 2) * 32;

    wx::fragment<wx::accumulator, 16, 16, 16, float> cf[2][2];
#pragma unroll
    for (int i = 0; i < 2; ++i)
#pragma unroll
        for (int j = 0; j < 2; ++j) wx::fill_fragment(cf[i][j], 0.0f);

    auto load_chunk = [&](int kc) {
        __half* smA = smh + (kc % 3) * STG_H;
        __half* smB = smA + STG_A;
        uint32_t sA = (uint32_t)__cvta_generic_to_shared(smA);
        uint32_t sB = (uint32_t)__cvta_generic_to_shared(smB);
        const __half* gA = A + m0 * HD + (size_t)kc * KT;
        const __half* gB = B + n0 * HD + (size_t)kc * KT;
#pragma unroll
        for (int i = 0; i < 2; ++i) {
            int p = tid + i * 256;
            int r = p >> 2, seg = p & 3;
            CP16(sA + (uint32_t)(r * LDTH + seg * 8) * 2u, gA + (size_t)r * HD + seg * 8);
        }
        {
            int r = tid >> 2, seg = tid & 3;
            CP16(sB + (uint32_t)(r * LDTH + seg * 8) * 2u, gB + (size_t)r * HD + seg * 8);
        }
        CP_COMMIT();
    };

    load_chunk(0);
    load_chunk(1);

    for (int kc = 0; kc < NC; ++kc) {
        if (kc < NC - 1) asm volatile("cp.async.wait_group 1;" ::: "memory");
        else             asm volatile("cp.async.wait_group 0;" ::: "memory");
        __syncthreads();
        if (kc + 2 < NC) load_chunk(kc + 2);

        __half* smA = smh + (kc % 3) * STG_H;
        __half* smB = smA + STG_A;
#pragma unroll
        for (int ks = 0; ks < 2; ++ks) {
            wx::fragment<wx::matrix_a, 16, 16, 16, __half, wx::row_major> af[2];
            wx::fragment<wx::matrix_b, 16, 16, 16, __half, wx::col_major> bf[2];
#pragma unroll
            for (int i = 0; i < 2; ++i)
                wx::load_matrix_sync(af[i], smA + (wm0 + i * 16) * LDTH + ks * 16, LDTH);
#pragma unroll
            for (int j = 0; j < 2; ++j)
                wx::load_matrix_sync(bf[j], smB + (wn0 + j * 16) * LDTH + ks * 16, LDTH);
#pragma unroll
            for (int i = 0; i < 2; ++i)
#pragma unroll
                for (int j = 0; j < 2; ++j)
                    wx::mma_sync(cf[i][j], af[i], bf[j], cf[i][j]);
        }
    }

    __syncthreads();
#pragma unroll
    for (int i = 0; i < 2; ++i)
#pragma unroll
        for (int j = 0; j < 2; ++j)
            wx::store_matrix_sync(gates + (wm0 + i * 16) * LDG + wn0 + j * 16,
                                  cf[i][j], LDG, wx::mem_row_major);
    __syncthreads();
}

__global__ void __launch_bounds__(256) fc_kernel(const float* __restrict__ bfc,
                                                 float* __restrict__ out) {
    extern __shared__ __half smh[];
    float* gates = (float*)smh;
    size_t n0 = (size_t)blockIdx.x * 64;
    size_t m0 = (size_t)blockIdx.y * 128;

    gemm16_fc(g_h, m0, g_Wfc, n0, smh, gates);

    const int tid = (int)threadIdx.x;
    const int cg = tid & 3;
    const int rr = tid >> 2;
#pragma unroll
    for (int p = 0; p < 2; ++p) {
        int r = rr + p * 64;
        size_t m = m0 + r;
#pragma unroll
        for (int q = 0; q < 4; ++q) {
            int c = cg * 16 + q * 4;
            float4 gv = *(const float4*)(gates + r * LDG + c);
            float4 bv = *(const float4*)(bfc + n0 + c);
            gv.x += bv.x; gv.y += bv.y; gv.z += bv.z; gv.w += bv.w;
            *(float4*)(out + m * DD + n0 + c) = gv;
        }
    }
}

// ---------------- launch ----------------
extern "C" void kernel_launch(void* const* d_in, const int* in_sizes, int n_in,
                              void* d_out, int out_size) {
    const float* hT  = (const float*)d_in[0];
    // d_in[1] = t (int32) — fixed 128 for this problem
    const float* Wih = (const float*)d_in[2];
    const float* Whh = (const float*)d_in[3];
    const float* bih = (const float*)d_in[4];
    const float* bhh = (const float*)d_in[5];
    const float* Wfc = (const float*)d_in[6];
    const float* bfc = (const float*)d_in[7];
    float* out = (float*)d_out;

    cudaFuncSetAttribute(lstm_persist, cudaFuncAttributeMaxDynamicSharedMemorySize, PERS_SMEM);
    cudaFuncSetAttribute(fc_kernel, cudaFuncAttributeMaxDynamicSharedMemorySize, FC_SMEM);

    prep_kernel<<<(4096 * HD) / 256, 256>>>(Wih, Whh, bih, bhh, Wfc, hT);

    lstm_persist<<<dim3(64, 2), NTHR, PERS_SMEM>>>();

    fc_kernel<<<dim3(4, 256), 256, FC_SMEM>>>(bfc, out);
}

// round 17
// speedup vs baseline: 1.3044x; 1.0204x over previous
#include <cuda_runtime.h>
#include <cuda_fp16.h>
#include <mma.h>
#include <cstdint>
#include <cstddef>

using namespace nvcuda;
namespace wx = nvcuda::wmma;

#define NB 256
#define HD 1024
#define DD 256
#define TT 128

// ---- persistent step kernel geometry (8 warps, warp tile 32x32, 4-stage pipe) ----
#define NTHR 256
#define KT2 64                    // k per chunk
#define NCH (HD / KT2)            // 16 chunks
#define NSTG 4                    // pipeline stages
#define LDA 72                    // A smem row stride (halves)
#define LDB 1032                  // B smem row stride (halves)
#define STGA (128 * LDA)          // halves per A stage (9216)
#define SMB_OFF (NSTG * STGA)
#define PERS_SMEM ((NSTG * STGA + 64 * LDB) * 2)   // 205824 B

// ---- fc kernel geometry ----
#define KT 32
#define NC (HD / KT)
#define LDTH 40
#define LDG 68
#define STG_A (128 * LDTH)
#define STG_B (64 * LDTH)
#define STG_H (STG_A + STG_B)
#define FC_SMEM (3 * STG_H * 2)

// ---------------- static device scratch ----------------
__device__ __half g_Wc[4096 * HD];              // gate-permuted (Wih+Whh)  8 MB
__device__ __half g_Wp[4096 * HD];              // gate-permuted Wih        8 MB
__device__ __half g_Wfc[DD * HD];
__device__ __half g_x0[NB * HD];
__device__ float  g_bp[4096];
__device__ __half g_h[(size_t)TT * NB * HD];    // hidden history fp16 (64 MB)
__device__ unsigned g_barcnt[64];               // per-half counters at [by*32]
__device__ volatile unsigned g_bargen[64];      // per-half generation at [by*32]

// hardware tanh (sm_75+): single MUFU op, ~2^-11 max error
__device__ __forceinline__ float ftanh(float z) {
    float r;
    asm("tanh.approx.f32 %0, %1;" : "=f"(r) : "f"(z));
    return r;
}
// sigmoid via tanh: sigma(z) = 0.5*tanh(z/2) + 0.5
__device__ __forceinline__ float sigm(float z) {
    return fmaf(ftanh(0.5f * z), 0.5f, 0.5f);
}

#define CP16(saddr, gptr) \
    asm volatile("cp.async.cg.shared.global [%0], [%1], 16;" :: "r"(saddr), "l"(gptr) : "memory")
#define CP_COMMIT() asm volatile("cp.async.commit_group;" ::: "memory")

// barrier over the 64 CTAs sharing one batch half (R9/R13-proven design)
__device__ __forceinline__ void half_barrier(int by) {
    __syncthreads();
    if (threadIdx.x == 0) {
        __threadfence();
        unsigned g = g_bargen[by * 32];
        if (atomicAdd(&g_barcnt[by * 32], 1u) == 63u) {
            g_barcnt[by * 32] = 0;
            __threadfence();
            g_bargen[by * 32] = g + 1;
        } else {
            while (g_bargen[by * 32] == g) { }
        }
    }
    __syncthreads();
}

// ---------------- prep ----------------
// Gate permutation matched to the mma accumulator layout (R13-proven):
// rowp: group=rowp>>4, w16=rowp&15 -> G=((w16>>3)<<1)|(w16&1), j=group*4+((w16&7)>>1)
__global__ void prep_kernel(const float* __restrict__ Wih, const float* __restrict__ Whh,
                            const float* __restrict__ bih, const float* __restrict__ bhh,
                            const float* __restrict__ Wfc, const float* __restrict__ hT) {
    size_t idx = (size_t)blockIdx.x * 256 + threadIdx.x;
    if (idx < (size_t)4096 * HD) {
        int k = (int)(idx & (HD - 1));
        int rowp = (int)(idx >> 10);
        int w16 = rowp & 15;
        int G = ((w16 >> 3) << 1) | (w16 & 1);
        int j = (rowp >> 4) * 4 + ((w16 & 7) >> 1);
        size_t src = (size_t)(G * HD + j) * HD + k;
        float a = Wih[src];
        g_Wp[idx] = __float2half_rn(a);
        g_Wc[idx] = __float2half_rn(a + Whh[src]);
    }
    if (idx < (size_t)DD * HD) g_Wfc[idx] = __float2half_rn(Wfc[idx]);
    if (idx < (size_t)NB * HD) g_x0[idx] = __float2half_rn(hT[idx]);
    if (idx < 4096) {
        int w16 = (int)(idx & 15);
        int G = ((w16 >> 3) << 1) | (w16 & 1);
        int j = ((int)(idx >> 4)) * 4 + ((w16 & 7) >> 1);
        g_bp[idx] = bih[G * HD + j] + bhh[G * HD + j];
    }
    if (idx < 64) { g_barcnt[idx] = 0u; *(unsigned*)&g_bargen[idx] = 0u; }
}

// ---------------- persistent LSTM ----------------
// grid (64, 2): n0 = bx*64 permuted gate cols (16 units), m0 = by*128 batch rows.
// 8 warps, warp tile 32x32; 4-stage cp.async pipeline (wait_group 2 slack);
// R9 atomic half-barrier; R13 register epilogue with hw-tanh activations.
__global__ void __launch_bounds__(NTHR) lstm_persist() {
    extern __shared__ __half smh[];
    __half* smB = smh + SMB_OFF;
    __half* hst = smh;                          // 128x16 halves staging (aliases stage 0)

    const int tid = (int)threadIdx.x;
    const int w = tid >> 5;
    const int lane = tid & 31;
    const int wm0 = (w & 3) * 32;
    const int wn0 = (w >> 2) * 32;
    const int fr = lane >> 2;                   // fragment row 0..7
    const int cq = lane & 3;                    // fragment col quad
    const int bx = (int)blockIdx.x;
    const int by = (int)blockIdx.y;
    const size_t n0 = (size_t)bx * 64;
    const size_t m0 = (size_t)by * 128;

    auto loadB = [&](const __half* __restrict__ Wsrc) {
        uint32_t sB = (uint32_t)__cvta_generic_to_shared(smB);
#pragma unroll
        for (int i = 0; i < 32; ++i) {
            int p = tid + i * NTHR;             // 0..8191
            int r = p >> 7;
            int sg = p & 127;
            CP16(sB + (uint32_t)(r * LDB + sg * 8) * 2u, Wsrc + (n0 + (size_t)r) * HD + sg * 8);
        }
        CP_COMMIT();
    };

    loadB(g_Wp);
    asm volatile("cp.async.wait_group 0;" ::: "memory");
    __syncthreads();

    float2 bif[2], bgo[2];
    int ul[2];
#pragma unroll
    for (int j = 0; j < 2; ++j) {
        bif[j] = *(const float2*)(g_bp + n0 + wn0 + 16 * j + 2 * cq);
        bgo[j] = *(const float2*)(g_bp + n0 + wn0 + 16 * j + 8 + 2 * cq);
        ul[j] = ((wn0 + 16 * j) >> 4) * 4 + cq;
    }

    float creg[8];
#pragma unroll
    for (int i = 0; i < 8; ++i) creg[i] = 0.0f;

    for (int t = 0; t < TT; ++t) {
        const __half* A = (t == 0) ? g_x0 : (g_h + (size_t)(t - 1) * NB * HD);

        auto loadA = [&](int kc) {
            uint32_t sA = (uint32_t)__cvta_generic_to_shared(smh + (kc % NSTG) * STGA);
            const __half* gA = A + m0 * HD + (size_t)kc * KT2;
#pragma unroll
            for (int i = 0; i < 4; ++i) {
                int p = tid + i * NTHR;         // 0..1023
                int r = p >> 3;
                int sg = p & 7;
                CP16(sA + (uint32_t)(r * LDA + sg * 8) * 2u, gA + (size_t)r * HD + sg * 8);
            }
            CP_COMMIT();
        };

        wx::fragment<wx::accumulator, 16, 16, 16, float> cf[2][2];
#pragma unroll
        for (int i = 0; i < 2; ++i)
#pragma unroll
            for (int j = 0; j < 2; ++j) wx::fill_fragment(cf[i][j], 0.0f);

        loadA(0);
        loadA(1);
        loadA(2);

        for (int kc = 0; kc < NCH; ++kc) {
            if (kc < NCH - 2)      asm volatile("cp.async.wait_group 2;" ::: "memory");
            else if (kc < NCH - 1) asm volatile("cp.async.wait_group 1;" ::: "memory");
            else                   asm volatile("cp.async.wait_group 0;" ::: "memory");
            __syncthreads();
            if (kc + 3 < NCH) loadA(kc + 3);    // overwrites stage consumed last iter

            const __half* smA = smh + (kc % NSTG) * STGA;
#pragma unroll
            for (int ks = 0; ks < 4; ++ks) {
                wx::fragment<wx::matrix_a, 16, 16, 16, __half, wx::row_major> af[2];
                wx::fragment<wx::matrix_b, 16, 16, 16, __half, wx::col_major> bf[2];
#pragma unroll
                for (int i = 0; i < 2; ++i)
                    wx::load_matrix_sync(af[i], smA + (wm0 + i * 16) * LDA + ks * 16, LDA);
#pragma unroll
                for (int j = 0; j < 2; ++j)
                    wx::load_matrix_sync(bf[j], smB + (wn0 + j * 16) * LDB + kc * KT2 + ks * 16, LDB);
#pragma unroll
                for (int i = 0; i < 2; ++i)
#pragma unroll
                    for (int j = 0; j < 2; ++j)
                        wx::mma_sync(cf[i][j], af[i], bf[j], cf[i][j]);
            }
        }

        __syncthreads();      // all ldsm done; stage 0 free for h staging

        // swap in combined weights after step 0 (overlaps register epilogue)
        if (t == 0) loadB(g_Wc);

        // ---- register epilogue (R13-proven accumulator layout, hw-tanh) ----
#pragma unroll
        for (int i = 0; i < 2; ++i) {
            int rA = wm0 + 16 * i + fr;
#pragma unroll
            for (int j = 0; j < 2; ++j) {
                const float* x = cf[i][j].x;
                float bi = bif[j].x, bfv = bif[j].y, bg = bgo[j].x, bo = bgo[j].y;
                {   // row rA
                    float iv = sigm(x[0] + bi);
                    float fv = sigm(x[1] + bfv);
                    float gg = ftanh(x[4] + bg);
                    float ov = sigm(x[5] + bo);
                    float c = fmaf(fv, creg[i * 4 + j], iv * gg);
                    creg[i * 4 + j] = c;
                    hst[rA * 16 + ul[j]] = __float2half_rn(ov * ftanh(c));
                }
                {   // row rA + 8
                    float iv = sigm(x[2] + bi);
                    float fv = sigm(x[3] + bfv);
                    float gg = ftanh(x[6] + bg);
                    float ov = sigm(x[7] + bo);
                    float c = fmaf(fv, creg[i * 4 + 2 + j], iv * gg);
                    creg[i * 4 + 2 + j] = c;
                    hst[(rA + 8) * 16 + ul[j]] = __float2half_rn(ov * ftanh(c));
                }
            }
        }

        if (t == 0) asm volatile("cp.async.wait_group 0;" ::: "memory");  // retire B swap
        __syncthreads();      // staging complete

        // coalesced h store: 128 rows x 32B, 2 threads per row
        {
            int row = tid >> 1, hf = tid & 1;
            uint4 v = *(const uint4*)((const char*)hst + row * 32 + hf * 16);
            __half* hbase = g_h + (size_t)t * NB * HD;
            *(uint4*)(hbase + (m0 + (size_t)row) * HD + bx * 16 + hf * 8) = v;
        }

        half_barrier(by);     // h[t] of this batch half visible to its 64 CTAs
    }
}

// ---------------- FC: out[32768,256] = h @ Wfc^T + b (unchanged) ----------
__device__ __forceinline__ void gemm16_fc(const __half* __restrict__ A, size_t m0,
                                          const __half* __restrict__ B, size_t n0,
                                          __half* smh, float* gates) {
    const int tid = (int)threadIdx.x;
    const int w = tid >> 5;
    const int wm0 = (w & 3) * 32;
    const int wn0 = (w >> 2) * 32;

    wx::fragment<wx::accumulator, 16, 16, 16, float> cf[2][2];
#pragma unroll
    for (int i = 0; i < 2; ++i)
#pragma unroll
        for (int j = 0; j < 2; ++j) wx::fill_fragment(cf[i][j], 0.0f);

    auto load_chunk = [&](int kc) {
        __half* smA = smh + (kc % 3) * STG_H;
        __half* smB = smA + STG_A;
        uint32_t sA = (uint32_t)__cvta_generic_to_shared(smA);
        uint32_t sB = (uint32_t)__cvta_generic_to_shared(smB);
        const __half* gA = A + m0 * HD + (size_t)kc * KT;
        const __half* gB = B + n0 * HD + (size_t)kc * KT;
#pragma unroll
        for (int i = 0; i < 2; ++i) {
            int p = tid + i * 256;
            int r = p >> 2, seg = p & 3;
            CP16(sA + (uint32_t)(r * LDTH + seg * 8) * 2u, gA + (size_t)r * HD + seg * 8);
        }
        {
            int r = tid >> 2, seg = tid & 3;
            CP16(sB + (uint32_t)(r * LDTH + seg * 8) * 2u, gB + (size_t)r * HD + seg * 8);
        }
        CP_COMMIT();
    };

    load_chunk(0);
    load_chunk(1);

    for (int kc = 0; kc < NC; ++kc) {
        if (kc < NC - 1) asm volatile("cp.async.wait_group 1;" ::: "memory");
        else             asm volatile("cp.async.wait_group 0;" ::: "memory");
        __syncthreads();
        if (kc + 2 < NC) load_chunk(kc + 2);

        __half* smA = smh + (kc % 3) * STG_H;
        __half* smB = smA + STG_A;
#pragma unroll
        for (int ks = 0; ks < 2; ++ks) {
            wx::fragment<wx::matrix_a, 16, 16, 16, __half, wx::row_major> af[2];
            wx::fragment<wx::matrix_b, 16, 16, 16, __half, wx::col_major> bf[2];
#pragma unroll
            for (int i = 0; i < 2; ++i)
                wx::load_matrix_sync(af[i], smA + (wm0 + i * 16) * LDTH + ks * 16, LDTH);
#pragma unroll
            for (int j = 0; j < 2; ++j)
                wx::load_matrix_sync(bf[j], smB + (wn0 + j * 16) * LDTH + ks * 16, LDTH);
#pragma unroll
            for (int i = 0; i < 2; ++i)
#pragma unroll
                for (int j = 0; j < 2; ++j)
                    wx::mma_sync(cf[i][j], af[i], bf[j], cf[i][j]);
        }
    }

    __syncthreads();
#pragma unroll
    for (int i = 0; i < 2; ++i)
#pragma unroll
        for (int j = 0; j < 2; ++j)
            wx::store_matrix_sync(gates + (wm0 + i * 16) * LDG + wn0 + j * 16,
                                  cf[i][j], LDG, wx::mem_row_major);
    __syncthreads();
}

__global__ void __launch_bounds__(256) fc_kernel(const float* __restrict__ bfc,
                                                 float* __restrict__ out) {
    extern __shared__ __half smh[];
    float* gates = (float*)smh;
    size_t n0 = (size_t)blockIdx.x * 64;
    size_t m0 = (size_t)blockIdx.y * 128;

    gemm16_fc(g_h, m0, g_Wfc, n0, smh, gates);

    const int tid = (int)threadIdx.x;
    const int cg = tid & 3;
    const int rr = tid >> 2;
#pragma unroll
    for (int p = 0; p < 2; ++p) {
        int r = rr + p * 64;
        size_t m = m0 + r;
#pragma unroll
        for (int q = 0; q < 4; ++q) {
            int c = cg * 16 + q * 4;
            float4 gv = *(const float4*)(gates + r * LDG + c);
            float4 bv = *(const float4*)(bfc + n0 + c);
            gv.x += bv.x; gv.y += bv.y; gv.z += bv.z; gv.w += bv.w;
            *(float4*)(out + m * DD + n0 + c) = gv;
        }
    }
}

// ---------------- launch ----------------
extern "C" void kernel_launch(void* const* d_in, const int* in_sizes, int n_in,
                              void* d_out, int out_size) {
    const float* hT  = (const float*)d_in[0];
    // d_in[1] = t (int32) — fixed 128 for this problem
    const float* Wih = (const float*)d_in[2];
    const float* Whh = (const float*)d_in[3];
    const float* bih = (const float*)d_in[4];
    const float* bhh = (const float*)d_in[5];
    const float* Wfc = (const float*)d_in[6];
    const float* bfc = (const float*)d_in[7];
    float* out = (float*)d_out;

    cudaFuncSetAttribute(lstm_persist, cudaFuncAttributeMaxDynamicSharedMemorySize, PERS_SMEM);
    cudaFuncSetAttribute(fc_kernel, cudaFuncAttributeMaxDynamicSharedMemorySize, FC_SMEM);

    prep_kernel<<<(4096 * HD) / 256, 256>>>(Wih, Whh, bih, bhh, Wfc, hT);

    lstm_persist<<<dim3(64, 2), NTHR, PERS_SMEM>>>();

    fc_kernel<<<dim3(4, 256), 256, FC_SMEM>>>(bfc, out);
}